// round 14
// baseline (speedup 1.0000x reference)
#include <cuda_runtime.h>
#include <cstdint>
#include <math.h>

#define NTHREADS 256
#define TM 64
#define SSTR 132                     /* 132 % 4 == 0, 132 % 32 == 4 */
#define ASTR 260                     /* 260 % 4 == 0, 260 % 32 == 4 */
#define TILE_F 4096                  /* 16 KB weight tile */

#define SA_OFF (TM * SSTR)           /* 8448  */
#define SW_OFF (SA_OFF + TM * ASTR)  /* 25088 */
#define SMEM_FLOATS (SW_OFF + 4 * TILE_F) /* 41472 */
#define SMEM_BYTES (SMEM_FLOATS * 4)      /* 165888 B */

typedef unsigned long long u64;

// k-pair-interleaved weights (constant; packed once per launch)
__device__ float W1P[128 * 256];
__device__ float W2P[256 * 128];
__device__ float WGP[256 * 128];

// ---------------- packed f32x2 (Blackwell FFMA2) ----------------
__device__ __forceinline__ u64 fma2(u64 a, u64 b, u64 c) {
    u64 d;
    asm("fma.rn.f32x2 %0, %1, %2, %3;" : "=l"(d) : "l"(a), "l"(b), "l"(c));
    return d;
}
__device__ __forceinline__ float sum2(u64 v) {
    float lo, hi;
    asm("mov.b64 {%0, %1}, %2;" : "=f"(lo), "=f"(hi) : "l"(v));
    return lo + hi;
}

// ---------------- cp.async ----------------
__device__ __forceinline__ void cp_async16(unsigned saddr, const void* g) {
    asm volatile("cp.async.ca.shared.global [%0], [%1], 16;" ::"r"(saddr), "l"(g));
}
__device__ __forceinline__ void cp_commit() {
    asm volatile("cp.async.commit_group;" ::: "memory");
}
__device__ __forceinline__ void cp_wait0() {
    asm volatile("cp.async.wait_group 0;" ::: "memory");
}
// half-scoped named barrier (128 threads)
__device__ __forceinline__ void barh(int bid) {
    asm volatile("bar.sync %0, 128;" ::"r"(bid) : "memory");
}
// one 16KB tile loaded by 128 threads (8 float4 each)
__device__ __forceinline__ void ldtile128(float* dst, const float* g, int htid) {
    unsigned s = (unsigned)__cvta_generic_to_shared(dst);
    const float4* g4 = (const float4*)g;
#pragma unroll
    for (int i = 0; i < 8; i++)
        cp_async16(s + (htid + i * 128) * 16, g4 + htid + i * 128);
    cp_commit();
}

__device__ __forceinline__ float gelu_f(float x) {
    return 0.5f * x * (1.0f + erff(x * 0.7071067811865476f));
}
__device__ __forceinline__ float sigmoid_f(float x) {
    return 1.0f / (1.0f + __expf(-x));
}

// ---------------- weight pre-pack: out[kp][n] = (in[2kp][n], in[2kp+1][n]) ---
__global__ void pack_weights_kernel(const float* __restrict__ w1,
                                    const float* __restrict__ w2,
                                    const float* __restrict__ wg) {
    int i = blockIdx.x * blockDim.x + threadIdx.x;  // 0 .. 49151
    int m = i >> 14;
    int r = i & 16383;
    if (m == 0) {
        int kp = r >> 8, n = r & 255;
        ((float2*)W1P)[r] = make_float2(w1[(2 * kp) * 256 + n], w1[(2 * kp + 1) * 256 + n]);
    } else if (m == 1) {
        int kp = r >> 7, n = r & 127;
        ((float2*)W2P)[r] = make_float2(w2[(2 * kp) * 128 + n], w2[(2 * kp + 1) * 128 + n]);
    } else {
        int kp = r >> 7, n = r & 127;
        ((float2*)WGP)[r] = make_float2(wg[(2 * kp) * 128 + n], wg[(2 * kp + 1) * 128 + n]);
    }
}

// ---------------- k-paired GEMM, warp-owned 8 rows x (Q*64) u64-cols ---------
// Q=4: N=256 (M1). Q=2: N=128 (M2/M3). Thread owns u64 cols q*64 + 2*lane,
// q = 0..Q-1, each col pair as one u64 acc of (even-k, odd-k) partials.
// A: SMEM rows (stride astr), LDS.128 broadcast per row per 4k.
// B: k-pair-packed weights in global, streamed via two 16KB half-owned buffers
// with half-scoped named barriers. ACCUMULATES into acc.
template <int Q, int NTILES>
__device__ __forceinline__ void gemm_h(const float* __restrict__ A0, int astr,
                                       const float* __restrict__ Bg,
                                       float* b0, float* b1, u64* acc,
                                       int lane, int bid, int htid) {
    constexpr int KQ = 16 / Q;  // kq (4k each) per tile
    ldtile128(b0, Bg, htid);
    cp_wait0();
    barh(bid);
    for (int t = 0; t < NTILES; t++) {
        if (t + 1 < NTILES)
            ldtile128(((t + 1) & 1) ? b1 : b0, Bg + (t + 1) * TILE_F, htid);
        const float* sB = (t & 1) ? b1 : b0;
        const float* At = A0 + t * (KQ * 4);
#pragma unroll
        for (int kq = 0; kq < KQ; kq++) {
            ulonglong2 a[8];
#pragma unroll
            for (int rr = 0; rr < 8; rr++)
                a[rr] = *(const ulonglong2*)(At + rr * astr + kq * 4);
#pragma unroll
            for (int j = 0; j < 2; j++) {
                const u64* bp = (const u64*)sB + (kq * 2 + j) * (Q * 64) + 2 * lane;
                u64 b[2 * Q];
#pragma unroll
                for (int q = 0; q < Q; q++)
                    *(ulonglong2*)&b[2 * q] = *(const ulonglong2*)(bp + q * 64);
#pragma unroll
                for (int rr = 0; rr < 8; rr++) {
                    u64 av = j ? a[rr].y : a[rr].x;
#pragma unroll
                    for (int c = 0; c < 2 * Q; c++)
                        acc[rr * 2 * Q + c] = fma2(av, b[c], acc[rr * 2 * Q + c]);
                }
            }
        }
        cp_wait0();
        barh(bid);
    }
}

// ---------------- main fused recurrent kernel ----------------
__global__ void __launch_bounds__(NTHREADS, 1)
TinyRecurrentWorkshop_69054484185493_kernel(
    const float* __restrict__ x,
    const float* __restrict__ ln_w, const float* __restrict__ ln_b,
    const float* __restrict__ b1, const float* __restrict__ b2,
    const float* __restrict__ bg,
    const int* __restrict__ passes_p,
    float* __restrict__ out) {
    extern __shared__ float smem[];
    float* sS = smem;            // state 64 x 132
    float* sA = smem + SA_OFF;   // h / act / refined : 64 x 260
    float* sW = smem + SW_OFF;   // 2 halves x 2 x 4096 weight buffers

    const int tid = threadIdx.x;
    const int w = tid >> 5, lane = tid & 31;
    const int half = tid >> 7, htid = tid & 127;
    const int bid = 1 + half;           // named barrier id per half
    const int wrow = w * 8;             // this warp's 8 rows (all phases)
    float* hb0 = sW + half * 2 * TILE_F;
    float* hb1 = hb0 + TILE_F;
    const long long rowBase = (long long)blockIdx.x * TM;

    // ---- load state tile (block-strided, one CTA sync) ----
    {
        const float4* xg = (const float4*)(x + rowBase * 128);
#pragma unroll
        for (int i = 0; i < 8; i++) {
            int idx = tid + i * NTHREADS;
            *(float4*)&sS[(idx >> 5) * SSTR + (idx & 31) * 4] = xg[idx];
        }
    }

    int npass = passes_p[0];
    if (npass < 1 || npass > 1024) {
        float f = __int_as_float(npass);
        npass = (int)f;
        if (npass < 1 || npass > 1024) npass = 8;
    }
    __syncthreads();

    const int r4 = lane >> 2;   // LN: 4 lanes per row, 8 rows per warp
    const int lq = lane & 3;

    for (int pass = 0; pass < npass; pass++) {
        // ---------- LayerNorm (warp-local): sS rows -> h in sA[:,0:128] ------
        {
            float4 xv[8];
            const float* sr = sS + (wrow + r4) * SSTR + lq * 32;
            float s = 0.f;
#pragma unroll
            for (int j = 0; j < 8; j++) {
                xv[j] = *(const float4*)(sr + j * 4);
                s += (xv[j].x + xv[j].y) + (xv[j].z + xv[j].w);
            }
            s += __shfl_xor_sync(0xFFFFFFFFu, s, 1);
            s += __shfl_xor_sync(0xFFFFFFFFu, s, 2);
            const float mu = s * (1.0f / 128.0f);
            float q = 0.f;
#pragma unroll
            for (int j = 0; j < 8; j++) {
                float d0 = xv[j].x - mu, d1 = xv[j].y - mu;
                float d2 = xv[j].z - mu, d3 = xv[j].w - mu;
                q += d0 * d0 + d1 * d1 + d2 * d2 + d3 * d3;
            }
            q += __shfl_xor_sync(0xFFFFFFFFu, q, 1);
            q += __shfl_xor_sync(0xFFFFFFFFu, q, 2);
            const float rstd = rsqrtf(q * (1.0f / 128.0f) + 1e-5f);
            float* hr = sA + (wrow + r4) * ASTR + lq * 32;
#pragma unroll
            for (int j = 0; j < 8; j++) {
                float4 wv = __ldg((const float4*)ln_w + lq * 8 + j);
                float4 bv = __ldg((const float4*)ln_b + lq * 8 + j);
                float4 h;
                h.x = (xv[j].x - mu) * rstd * wv.x + bv.x;
                h.y = (xv[j].y - mu) * rstd * wv.y + bv.y;
                h.z = (xv[j].z - mu) * rstd * wv.z + bv.z;
                h.w = (xv[j].w - mu) * rstd * wv.w + bv.w;
                *(float4*)(hr + j * 4) = h;
            }
        }
        __syncwarp();  // h visible warp-wide (A reads broadcast across lanes)

        // ---------- M1: g = h @ w1  (rows own, N=256, K=128) ----------
        u64 acc1[64];
#pragma unroll
        for (int i = 0; i < 64; i++) acc1[i] = 0ULL;
        gemm_h<4, 8>(sA + wrow * ASTR, ASTR, W1P, hb0, hb1, acc1, lane, bid, htid);

        // gelu(g + b1) -> sA rows own, cols 0..255
#pragma unroll
        for (int rr = 0; rr < 8; rr++) {
            float* ar = sA + (wrow + rr) * ASTR;
#pragma unroll
            for (int q = 0; q < 4; q++) {
                int c0 = q * 64 + 2 * lane;
                float2 bb = __ldg((const float2*)(b1 + c0));
                float2 o;
                o.x = gelu_f(sum2(acc1[rr * 8 + 2 * q + 0]) + bb.x);
                o.y = gelu_f(sum2(acc1[rr * 8 + 2 * q + 1]) + bb.y);
                *(float2*)(ar + c0) = o;
            }
        }
        __syncwarp();

        // ---------- M2: refined = act @ w2 + b2  (N=128, K=256) ----------
        u64 acc2[32];
#pragma unroll
        for (int i = 0; i < 32; i++) acc2[i] = 0ULL;
        gemm_h<2, 8>(sA + wrow * ASTR, ASTR, W2P, hb0, hb1, acc2, lane, bid, htid);

        float2 rf[16];  // refined values this thread owns
#pragma unroll
        for (int rr = 0; rr < 8; rr++) {
            float* ar = sA + (wrow + rr) * ASTR;
#pragma unroll
            for (int q = 0; q < 2; q++) {
                int c0 = q * 64 + 2 * lane;
                float2 bb = __ldg((const float2*)(b2 + c0));
                float2 v;
                v.x = sum2(acc2[rr * 4 + 2 * q + 0]) + bb.x;
                v.y = sum2(acc2[rr * 4 + 2 * q + 1]) + bb.y;
                rf[rr * 2 + q] = v;
                *(float2*)(ar + c0) = v;  // refined -> sA cols 0..127 (act dead)
            }
        }
        __syncwarp();

        // ---------- M3: z = state @ wg_s + refined @ wg_r (accumulated) ------
        u64 acc3[32];
#pragma unroll
        for (int i = 0; i < 32; i++) acc3[i] = 0ULL;
        gemm_h<2, 4>(sS + wrow * SSTR, SSTR, WGP, hb0, hb1, acc3, lane, bid, htid);
        gemm_h<2, 4>(sA + wrow * ASTR, ASTR, WGP + 16384, hb0, hb1, acc3, lane, bid, htid);

        // gate + residual update (same ownership -> warp-local)
#pragma unroll
        for (int rr = 0; rr < 8; rr++) {
            float* srw = sS + (wrow + rr) * SSTR;
#pragma unroll
            for (int q = 0; q < 2; q++) {
                int c0 = q * 64 + 2 * lane;
                float2 bb = __ldg((const float2*)(bg + c0));
                float g0 = sigmoid_f(sum2(acc3[rr * 4 + 2 * q + 0]) + bb.x);
                float g1 = sigmoid_f(sum2(acc3[rr * 4 + 2 * q + 1]) + bb.y);
                float2 st = *(const float2*)(srw + c0);
                st.x += g0 * rf[rr * 2 + q].x;
                st.y += g1 * rf[rr * 2 + q].y;
                *(float2*)(srw + c0) = st;
            }
        }
        __syncwarp();  // state visible warp-wide for next pass's LN
    }

    // ---- store result (block-strided; sync across warps once) ----
    __syncthreads();
    {
        float4* og = (float4*)(out + rowBase * 128);
#pragma unroll
        for (int i = 0; i < 8; i++) {
            int idx = tid + i * NTHREADS;
            og[idx] = *(const float4*)&sS[(idx >> 5) * SSTR + (idx & 31) * 4];
        }
    }
}

extern "C" void kernel_launch(void* const* d_in, const int* in_sizes, int n_in,
                              void* d_out, int out_size) {
    const float* x    = (const float*)d_in[0];
    const float* ln_w = (const float*)d_in[1];
    const float* ln_b = (const float*)d_in[2];
    const float* w1   = (const float*)d_in[3];
    const float* b1   = (const float*)d_in[4];
    const float* w2   = (const float*)d_in[5];
    const float* b2   = (const float*)d_in[6];
    const float* wg   = (const float*)d_in[7];
    const float* bg   = (const float*)d_in[8];
    const int* passes = (const int*)d_in[9];
    float* out = (float*)d_out;

    pack_weights_kernel<<<192, 256>>>(w1, w2, wg);

    const int nrows = in_sizes[0] / 128;
    const int blocks = nrows / TM;

    cudaFuncSetAttribute(TinyRecurrentWorkshop_69054484185493_kernel,
                         cudaFuncAttributeMaxDynamicSharedMemorySize, SMEM_BYTES);
    TinyRecurrentWorkshop_69054484185493_kernel<<<blocks, NTHREADS, SMEM_BYTES>>>(
        x, ln_w, ln_b, b1, b2, bg, passes, out);
}

// round 15
// speedup vs baseline: 1.0005x; 1.0005x over previous
#include <cuda_runtime.h>
#include <cstdint>
#include <math.h>

#define NTHREADS 256
#define TM 64
#define SSTR 132                     /* 132 % 4 == 0, 132 % 32 == 4 */
#define ASTR 260                     /* 260 % 4 == 0, 260 % 32 == 4 */
#define TILE_F 4096                  /* 16 KB weight tile */

#define SA_OFF (TM * SSTR)           /* 8448  */
#define SW_OFF (SA_OFF + TM * ASTR)  /* 25088 */
#define SMEM_FLOATS (SW_OFF + 4 * TILE_F) /* 41472 */
#define SMEM_BYTES (SMEM_FLOATS * 4)      /* 165888 B */

typedef unsigned long long u64;

// k-pair-interleaved weights (constant; packed once per launch)
__device__ float W1P[128 * 256];
__device__ float W2P[256 * 128];
__device__ float WGP[256 * 128];

// ---------------- packed f32x2 (Blackwell FFMA2) ----------------
__device__ __forceinline__ u64 fma2(u64 a, u64 b, u64 c) {
    u64 d;
    asm("fma.rn.f32x2 %0, %1, %2, %3;" : "=l"(d) : "l"(a), "l"(b), "l"(c));
    return d;
}
__device__ __forceinline__ float sum2(u64 v) {
    float lo, hi;
    asm("mov.b64 {%0, %1}, %2;" : "=f"(lo), "=f"(hi) : "l"(v));
    return lo + hi;
}

// ---------------- cp.async ----------------
__device__ __forceinline__ void cp_async16(unsigned saddr, const void* g) {
    asm volatile("cp.async.ca.shared.global [%0], [%1], 16;" ::"r"(saddr), "l"(g));
}
__device__ __forceinline__ void cp_commit() {
    asm volatile("cp.async.commit_group;" ::: "memory");
}
__device__ __forceinline__ void cp_wait0() {
    asm volatile("cp.async.wait_group 0;" ::: "memory");
}
// half-scoped named barrier (128 threads)
__device__ __forceinline__ void barh(int bid) {
    asm volatile("bar.sync %0, 128;" ::"r"(bid) : "memory");
}
// one 16KB tile loaded by 128 threads (8 float4 each)
__device__ __forceinline__ void ldtile128(float* dst, const float* g, int htid) {
    unsigned s = (unsigned)__cvta_generic_to_shared(dst);
    const float4* g4 = (const float4*)g;
#pragma unroll
    for (int i = 0; i < 8; i++)
        cp_async16(s + (htid + i * 128) * 16, g4 + htid + i * 128);
    cp_commit();
}

__device__ __forceinline__ float gelu_f(float x) {
    return 0.5f * x * (1.0f + erff(x * 0.7071067811865476f));
}
__device__ __forceinline__ float sigmoid_f(float x) {
    return 1.0f / (1.0f + __expf(-x));
}

// ---------------- weight pre-pack: out[kp][n] = (in[2kp][n], in[2kp+1][n]) ---
__global__ void pack_weights_kernel(const float* __restrict__ w1,
                                    const float* __restrict__ w2,
                                    const float* __restrict__ wg) {
    int i = blockIdx.x * blockDim.x + threadIdx.x;  // 0 .. 49151
    int m = i >> 14;
    int r = i & 16383;
    if (m == 0) {
        int kp = r >> 8, n = r & 255;
        ((float2*)W1P)[r] = make_float2(w1[(2 * kp) * 256 + n], w1[(2 * kp + 1) * 256 + n]);
    } else if (m == 1) {
        int kp = r >> 7, n = r & 127;
        ((float2*)W2P)[r] = make_float2(w2[(2 * kp) * 128 + n], w2[(2 * kp + 1) * 128 + n]);
    } else {
        int kp = r >> 7, n = r & 127;
        ((float2*)WGP)[r] = make_float2(wg[(2 * kp) * 128 + n], wg[(2 * kp + 1) * 128 + n]);
    }
}

// ---------------- k-paired GEMM, warp-owned 8 rows x (Q*64) u64-cols ---------
// Q=4: N=256 (M1). Q=2: N=128 (M2/M3). Thread owns u64 cols q*64 + 2*lane,
// q = 0..Q-1, each col pair as one u64 acc of (even-k, odd-k) partials.
// A: SMEM rows (stride astr), LDS.128 broadcast per row per 4k.
// B: k-pair-packed weights in global, streamed via two 16KB half-owned buffers
// with half-scoped named barriers. ACCUMULATES into acc.
template <int Q, int NTILES>
__device__ __forceinline__ void gemm_h(const float* __restrict__ A0, int astr,
                                       const float* __restrict__ Bg,
                                       float* b0, float* b1, u64* acc,
                                       int lane, int bid, int htid) {
    constexpr int KQ = 16 / Q;  // kq (4k each) per tile
    ldtile128(b0, Bg, htid);
    cp_wait0();
    barh(bid);
    for (int t = 0; t < NTILES; t++) {
        if (t + 1 < NTILES)
            ldtile128(((t + 1) & 1) ? b1 : b0, Bg + (t + 1) * TILE_F, htid);
        const float* sB = (t & 1) ? b1 : b0;
        const float* At = A0 + t * (KQ * 4);
#pragma unroll
        for (int kq = 0; kq < KQ; kq++) {
            ulonglong2 a[8];
#pragma unroll
            for (int rr = 0; rr < 8; rr++)
                a[rr] = *(const ulonglong2*)(At + rr * astr + kq * 4);
#pragma unroll
            for (int j = 0; j < 2; j++) {
                const u64* bp = (const u64*)sB + (kq * 2 + j) * (Q * 64) + 2 * lane;
                u64 b[2 * Q];
#pragma unroll
                for (int q = 0; q < Q; q++)
                    *(ulonglong2*)&b[2 * q] = *(const ulonglong2*)(bp + q * 64);
#pragma unroll
                for (int rr = 0; rr < 8; rr++) {
                    u64 av = j ? a[rr].y : a[rr].x;
#pragma unroll
                    for (int c = 0; c < 2 * Q; c++)
                        acc[rr * 2 * Q + c] = fma2(av, b[c], acc[rr * 2 * Q + c]);
                }
            }
        }
        cp_wait0();
        barh(bid);
    }
}

// ---------------- main fused recurrent kernel ----------------
__global__ void __launch_bounds__(NTHREADS, 1)
TinyRecurrentWorkshop_69054484185493_kernel(
    const float* __restrict__ x,
    const float* __restrict__ ln_w, const float* __restrict__ ln_b,
    const float* __restrict__ b1, const float* __restrict__ b2,
    const float* __restrict__ bg,
    const int* __restrict__ passes_p,
    float* __restrict__ out) {
    extern __shared__ float smem[];
    float* sS = smem;            // state 64 x 132
    float* sA = smem + SA_OFF;   // h / act / refined : 64 x 260
    float* sW = smem + SW_OFF;   // 2 halves x 2 x 4096 weight buffers

    const int tid = threadIdx.x;
    const int w = tid >> 5, lane = tid & 31;
    const int half = tid >> 7, htid = tid & 127;
    const int bid = 1 + half;           // named barrier id per half
    const int wrow = w * 8;             // this warp's 8 rows (all phases)
    float* hb0 = sW + half * 2 * TILE_F;
    float* hb1 = hb0 + TILE_F;
    const long long rowBase = (long long)blockIdx.x * TM;

    // ---- load state tile (block-strided, one CTA sync) ----
    {
        const float4* xg = (const float4*)(x + rowBase * 128);
#pragma unroll
        for (int i = 0; i < 8; i++) {
            int idx = tid + i * NTHREADS;
            *(float4*)&sS[(idx >> 5) * SSTR + (idx & 31) * 4] = xg[idx];
        }
    }

    int npass = passes_p[0];
    if (npass < 1 || npass > 1024) {
        float f = __int_as_float(npass);
        npass = (int)f;
        if (npass < 1 || npass > 1024) npass = 8;
    }
    __syncthreads();

    const int r4 = lane >> 2;   // LN: 4 lanes per row, 8 rows per warp
    const int lq = lane & 3;

    for (int pass = 0; pass < npass; pass++) {
        // ---------- LayerNorm (warp-local): sS rows -> h in sA[:,0:128] ------
        {
            float4 xv[8];
            const float* sr = sS + (wrow + r4) * SSTR + lq * 32;
            float s = 0.f;
#pragma unroll
            for (int j = 0; j < 8; j++) {
                xv[j] = *(const float4*)(sr + j * 4);
                s += (xv[j].x + xv[j].y) + (xv[j].z + xv[j].w);
            }
            s += __shfl_xor_sync(0xFFFFFFFFu, s, 1);
            s += __shfl_xor_sync(0xFFFFFFFFu, s, 2);
            const float mu = s * (1.0f / 128.0f);
            float q = 0.f;
#pragma unroll
            for (int j = 0; j < 8; j++) {
                float d0 = xv[j].x - mu, d1 = xv[j].y - mu;
                float d2 = xv[j].z - mu, d3 = xv[j].w - mu;
                q += d0 * d0 + d1 * d1 + d2 * d2 + d3 * d3;
            }
            q += __shfl_xor_sync(0xFFFFFFFFu, q, 1);
            q += __shfl_xor_sync(0xFFFFFFFFu, q, 2);
            const float rstd = rsqrtf(q * (1.0f / 128.0f) + 1e-5f);
            float* hr = sA + (wrow + r4) * ASTR + lq * 32;
#pragma unroll
            for (int j = 0; j < 8; j++) {
                float4 wv = __ldg((const float4*)ln_w + lq * 8 + j);
                float4 bv = __ldg((const float4*)ln_b + lq * 8 + j);
                float4 h;
                h.x = (xv[j].x - mu) * rstd * wv.x + bv.x;
                h.y = (xv[j].y - mu) * rstd * wv.y + bv.y;
                h.z = (xv[j].z - mu) * rstd * wv.z + bv.z;
                h.w = (xv[j].w - mu) * rstd * wv.w + bv.w;
                *(float4*)(hr + j * 4) = h;
            }
        }
        __syncwarp();  // h visible warp-wide (A reads broadcast across lanes)

        // ---------- M1: g = h @ w1  (rows own, N=256, K=128) ----------
        u64 acc1[64];
#pragma unroll
        for (int i = 0; i < 64; i++) acc1[i] = 0ULL;
        gemm_h<4, 8>(sA + wrow * ASTR, ASTR, W1P, hb0, hb1, acc1, lane, bid, htid);

        // gelu(g + b1) -> sA rows own, cols 0..255
#pragma unroll
        for (int rr = 0; rr < 8; rr++) {
            float* ar = sA + (wrow + rr) * ASTR;
#pragma unroll
            for (int q = 0; q < 4; q++) {
                int c0 = q * 64 + 2 * lane;
                float2 bb = __ldg((const float2*)(b1 + c0));
                float2 o;
                o.x = gelu_f(sum2(acc1[rr * 8 + 2 * q + 0]) + bb.x);
                o.y = gelu_f(sum2(acc1[rr * 8 + 2 * q + 1]) + bb.y);
                *(float2*)(ar + c0) = o;
            }
        }
        __syncwarp();

        // ---------- M2: refined = act @ w2 + b2  (N=128, K=256) ----------
        u64 acc2[32];
#pragma unroll
        for (int i = 0; i < 32; i++) acc2[i] = 0ULL;
        gemm_h<2, 8>(sA + wrow * ASTR, ASTR, W2P, hb0, hb1, acc2, lane, bid, htid);

        float2 rf[16];  // refined values this thread owns
#pragma unroll
        for (int rr = 0; rr < 8; rr++) {
            float* ar = sA + (wrow + rr) * ASTR;
#pragma unroll
            for (int q = 0; q < 2; q++) {
                int c0 = q * 64 + 2 * lane;
                float2 bb = __ldg((const float2*)(b2 + c0));
                float2 v;
                v.x = sum2(acc2[rr * 4 + 2 * q + 0]) + bb.x;
                v.y = sum2(acc2[rr * 4 + 2 * q + 1]) + bb.y;
                rf[rr * 2 + q] = v;
                *(float2*)(ar + c0) = v;  // refined -> sA cols 0..127 (act dead)
            }
        }
        __syncwarp();

        // ---------- M3: z = state @ wg_s + refined @ wg_r (accumulated) ------
        u64 acc3[32];
#pragma unroll
        for (int i = 0; i < 32; i++) acc3[i] = 0ULL;
        gemm_h<2, 4>(sS + wrow * SSTR, SSTR, WGP, hb0, hb1, acc3, lane, bid, htid);
        gemm_h<2, 4>(sA + wrow * ASTR, ASTR, WGP + 16384, hb0, hb1, acc3, lane, bid, htid);

        // gate + residual update (same ownership -> warp-local)
#pragma unroll
        for (int rr = 0; rr < 8; rr++) {
            float* srw = sS + (wrow + rr) * SSTR;
#pragma unroll
            for (int q = 0; q < 2; q++) {
                int c0 = q * 64 + 2 * lane;
                float2 bb = __ldg((const float2*)(bg + c0));
                float g0 = sigmoid_f(sum2(acc3[rr * 4 + 2 * q + 0]) + bb.x);
                float g1 = sigmoid_f(sum2(acc3[rr * 4 + 2 * q + 1]) + bb.y);
                float2 st = *(const float2*)(srw + c0);
                st.x += g0 * rf[rr * 2 + q].x;
                st.y += g1 * rf[rr * 2 + q].y;
                *(float2*)(srw + c0) = st;
            }
        }
        __syncwarp();  // state visible warp-wide for next pass's LN
    }

    // ---- store result (block-strided; sync across warps once) ----
    __syncthreads();
    {
        float4* og = (float4*)(out + rowBase * 128);
#pragma unroll
        for (int i = 0; i < 8; i++) {
            int idx = tid + i * NTHREADS;
            og[idx] = *(const float4*)&sS[(idx >> 5) * SSTR + (idx & 31) * 4];
        }
    }
}

extern "C" void kernel_launch(void* const* d_in, const int* in_sizes, int n_in,
                              void* d_out, int out_size) {
    const float* x    = (const float*)d_in[0];
    const float* ln_w = (const float*)d_in[1];
    const float* ln_b = (const float*)d_in[2];
    const float* w1   = (const float*)d_in[3];
    const float* b1   = (const float*)d_in[4];
    const float* w2   = (const float*)d_in[5];
    const float* b2   = (const float*)d_in[6];
    const float* wg   = (const float*)d_in[7];
    const float* bg   = (const float*)d_in[8];
    const int* passes = (const int*)d_in[9];
    float* out = (float*)d_out;

    pack_weights_kernel<<<192, 256>>>(w1, w2, wg);

    const int nrows = in_sizes[0] / 128;
    const int blocks = nrows / TM;

    cudaFuncSetAttribute(TinyRecurrentWorkshop_69054484185493_kernel,
                         cudaFuncAttributeMaxDynamicSharedMemorySize, SMEM_BYTES);
    TinyRecurrentWorkshop_69054484185493_kernel<<<blocks, NTHREADS, SMEM_BYTES>>>(
        x, ln_w, ln_b, b1, b2, bg, passes, out);
}

// round 16
// speedup vs baseline: 1.0008x; 1.0003x over previous
#include <cuda_runtime.h>
#include <cstdint>
#include <math.h>

#define NTHREADS 256
#define TM 64
#define SSTR 132                     /* 132 % 4 == 0, 132 % 32 == 4 */
#define ASTR 260                     /* 260 % 4 == 0, 260 % 32 == 4 */
#define TILE_F 4096                  /* 16 KB weight tile */

#define SA_OFF (TM * SSTR)           /* 8448  */
#define SW_OFF (SA_OFF + TM * ASTR)  /* 25088 */
#define SMEM_FLOATS (SW_OFF + 4 * TILE_F) /* 41472 */
#define SMEM_BYTES (SMEM_FLOATS * 4)      /* 165888 B */

typedef unsigned long long u64;

// k-pair-interleaved weights (constant; packed once per launch)
__device__ float W1P[128 * 256];
__device__ float W2P[256 * 128];
__device__ float WGP[256 * 128];

// ---------------- packed f32x2 (Blackwell FFMA2) ----------------
__device__ __forceinline__ u64 fma2(u64 a, u64 b, u64 c) {
    u64 d;
    asm("fma.rn.f32x2 %0, %1, %2, %3;" : "=l"(d) : "l"(a), "l"(b), "l"(c));
    return d;
}
__device__ __forceinline__ float sum2(u64 v) {
    float lo, hi;
    asm("mov.b64 {%0, %1}, %2;" : "=f"(lo), "=f"(hi) : "l"(v));
    return lo + hi;
}

// ---------------- cp.async ----------------
__device__ __forceinline__ void cp_async16(unsigned saddr, const void* g) {
    asm volatile("cp.async.ca.shared.global [%0], [%1], 16;" ::"r"(saddr), "l"(g));
}
__device__ __forceinline__ void cp_commit() {
    asm volatile("cp.async.commit_group;" ::: "memory");
}
__device__ __forceinline__ void cp_wait0() {
    asm volatile("cp.async.wait_group 0;" ::: "memory");
}
// half-scoped named barrier (128 threads)
__device__ __forceinline__ void barh(int bid) {
    asm volatile("bar.sync %0, 128;" ::"r"(bid) : "memory");
}
// one 16KB tile loaded by 128 threads (8 float4 each)
__device__ __forceinline__ void ldtile128(float* dst, const float* g, int htid) {
    unsigned s = (unsigned)__cvta_generic_to_shared(dst);
    const float4* g4 = (const float4*)g;
#pragma unroll
    for (int i = 0; i < 8; i++)
        cp_async16(s + (htid + i * 128) * 16, g4 + htid + i * 128);
    cp_commit();
}

__device__ __forceinline__ float gelu_f(float x) {
    return 0.5f * x * (1.0f + erff(x * 0.7071067811865476f));
}
__device__ __forceinline__ float sigmoid_f(float x) {
    return 1.0f / (1.0f + __expf(-x));
}

// ---------------- weight pre-pack: out[kp][n] = (in[2kp][n], in[2kp+1][n]) ---
__global__ void pack_weights_kernel(const float* __restrict__ w1,
                                    const float* __restrict__ w2,
                                    const float* __restrict__ wg) {
    int i = blockIdx.x * blockDim.x + threadIdx.x;  // 0 .. 49151
    int m = i >> 14;
    int r = i & 16383;
    if (m == 0) {
        int kp = r >> 8, n = r & 255;
        ((float2*)W1P)[r] = make_float2(w1[(2 * kp) * 256 + n], w1[(2 * kp + 1) * 256 + n]);
    } else if (m == 1) {
        int kp = r >> 7, n = r & 127;
        ((float2*)W2P)[r] = make_float2(w2[(2 * kp) * 128 + n], w2[(2 * kp + 1) * 128 + n]);
    } else {
        int kp = r >> 7, n = r & 127;
        ((float2*)WGP)[r] = make_float2(wg[(2 * kp) * 128 + n], wg[(2 * kp + 1) * 128 + n]);
    }
}

// ---------------- k-paired GEMM, warp-owned 8 rows x (Q*64) u64-cols ---------
// Q=4: N=256 (M1). Q=2: N=128 (M2/M3). Thread owns u64 cols q*64 + 2*lane,
// q = 0..Q-1, each col pair as one u64 acc of (even-k, odd-k) partials.
// A: SMEM rows (stride astr), LDS.128 broadcast per row per 4k.
// B: k-pair-packed weights in global, streamed via two 16KB half-owned buffers
// with half-scoped named barriers. ACCUMULATES into acc.
template <int Q, int NTILES>
__device__ __forceinline__ void gemm_h(const float* __restrict__ A0, int astr,
                                       const float* __restrict__ Bg,
                                       float* b0, float* b1, u64* acc,
                                       int lane, int bid, int htid) {
    constexpr int KQ = 16 / Q;  // kq (4k each) per tile
    ldtile128(b0, Bg, htid);
    cp_wait0();
    barh(bid);
    for (int t = 0; t < NTILES; t++) {
        if (t + 1 < NTILES)
            ldtile128(((t + 1) & 1) ? b1 : b0, Bg + (t + 1) * TILE_F, htid);
        const float* sB = (t & 1) ? b1 : b0;
        const float* At = A0 + t * (KQ * 4);
#pragma unroll
        for (int kq = 0; kq < KQ; kq++) {
            ulonglong2 a[8];
#pragma unroll
            for (int rr = 0; rr < 8; rr++)
                a[rr] = *(const ulonglong2*)(At + rr * astr + kq * 4);
#pragma unroll
            for (int j = 0; j < 2; j++) {
                const u64* bp = (const u64*)sB + (kq * 2 + j) * (Q * 64) + 2 * lane;
                u64 b[2 * Q];
#pragma unroll
                for (int q = 0; q < Q; q++)
                    *(ulonglong2*)&b[2 * q] = *(const ulonglong2*)(bp + q * 64);
#pragma unroll
                for (int rr = 0; rr < 8; rr++) {
                    u64 av = j ? a[rr].y : a[rr].x;
#pragma unroll
                    for (int c = 0; c < 2 * Q; c++)
                        acc[rr * 2 * Q + c] = fma2(av, b[c], acc[rr * 2 * Q + c]);
                }
            }
        }
        cp_wait0();
        barh(bid);
    }
}

// ---------------- main fused recurrent kernel ----------------
__global__ void __launch_bounds__(NTHREADS, 1)
TinyRecurrentWorkshop_69054484185493_kernel(
    const float* __restrict__ x,
    const float* __restrict__ ln_w, const float* __restrict__ ln_b,
    const float* __restrict__ b1, const float* __restrict__ b2,
    const float* __restrict__ bg,
    const int* __restrict__ passes_p,
    float* __restrict__ out) {
    extern __shared__ float smem[];
    float* sS = smem;            // state 64 x 132
    float* sA = smem + SA_OFF;   // h / act / refined : 64 x 260
    float* sW = smem + SW_OFF;   // 2 halves x 2 x 4096 weight buffers

    const int tid = threadIdx.x;
    const int w = tid >> 5, lane = tid & 31;
    const int half = tid >> 7, htid = tid & 127;
    const int bid = 1 + half;           // named barrier id per half
    const int wrow = w * 8;             // this warp's 8 rows (all phases)
    float* hb0 = sW + half * 2 * TILE_F;
    float* hb1 = hb0 + TILE_F;
    const long long rowBase = (long long)blockIdx.x * TM;

    // ---- load state tile (block-strided, one CTA sync) ----
    {
        const float4* xg = (const float4*)(x + rowBase * 128);
#pragma unroll
        for (int i = 0; i < 8; i++) {
            int idx = tid + i * NTHREADS;
            *(float4*)&sS[(idx >> 5) * SSTR + (idx & 31) * 4] = xg[idx];
        }
    }

    int npass = passes_p[0];
    if (npass < 1 || npass > 1024) {
        float f = __int_as_float(npass);
        npass = (int)f;
        if (npass < 1 || npass > 1024) npass = 8;
    }
    __syncthreads();

    const int r4 = lane >> 2;   // LN: 4 lanes per row, 8 rows per warp
    const int lq = lane & 3;

    for (int pass = 0; pass < npass; pass++) {
        // ---------- LayerNorm (warp-local): sS rows -> h in sA[:,0:128] ------
        {
            float4 xv[8];
            const float* sr = sS + (wrow + r4) * SSTR + lq * 32;
            float s = 0.f;
#pragma unroll
            for (int j = 0; j < 8; j++) {
                xv[j] = *(const float4*)(sr + j * 4);
                s += (xv[j].x + xv[j].y) + (xv[j].z + xv[j].w);
            }
            s += __shfl_xor_sync(0xFFFFFFFFu, s, 1);
            s += __shfl_xor_sync(0xFFFFFFFFu, s, 2);
            const float mu = s * (1.0f / 128.0f);
            float q = 0.f;
#pragma unroll
            for (int j = 0; j < 8; j++) {
                float d0 = xv[j].x - mu, d1 = xv[j].y - mu;
                float d2 = xv[j].z - mu, d3 = xv[j].w - mu;
                q += d0 * d0 + d1 * d1 + d2 * d2 + d3 * d3;
            }
            q += __shfl_xor_sync(0xFFFFFFFFu, q, 1);
            q += __shfl_xor_sync(0xFFFFFFFFu, q, 2);
            const float rstd = rsqrtf(q * (1.0f / 128.0f) + 1e-5f);
            float* hr = sA + (wrow + r4) * ASTR + lq * 32;
#pragma unroll
            for (int j = 0; j < 8; j++) {
                float4 wv = __ldg((const float4*)ln_w + lq * 8 + j);
                float4 bv = __ldg((const float4*)ln_b + lq * 8 + j);
                float4 h;
                h.x = (xv[j].x - mu) * rstd * wv.x + bv.x;
                h.y = (xv[j].y - mu) * rstd * wv.y + bv.y;
                h.z = (xv[j].z - mu) * rstd * wv.z + bv.z;
                h.w = (xv[j].w - mu) * rstd * wv.w + bv.w;
                *(float4*)(hr + j * 4) = h;
            }
        }
        __syncwarp();  // h visible warp-wide (A reads broadcast across lanes)

        // ---------- M1: g = h @ w1  (rows own, N=256, K=128) ----------
        u64 acc1[64];
#pragma unroll
        for (int i = 0; i < 64; i++) acc1[i] = 0ULL;
        gemm_h<4, 8>(sA + wrow * ASTR, ASTR, W1P, hb0, hb1, acc1, lane, bid, htid);

        // gelu(g + b1) -> sA rows own, cols 0..255
#pragma unroll
        for (int rr = 0; rr < 8; rr++) {
            float* ar = sA + (wrow + rr) * ASTR;
#pragma unroll
            for (int q = 0; q < 4; q++) {
                int c0 = q * 64 + 2 * lane;
                float2 bb = __ldg((const float2*)(b1 + c0));
                float2 o;
                o.x = gelu_f(sum2(acc1[rr * 8 + 2 * q + 0]) + bb.x);
                o.y = gelu_f(sum2(acc1[rr * 8 + 2 * q + 1]) + bb.y);
                *(float2*)(ar + c0) = o;
            }
        }
        __syncwarp();

        // ---------- M2: refined = act @ w2 + b2  (N=128, K=256) ----------
        u64 acc2[32];
#pragma unroll
        for (int i = 0; i < 32; i++) acc2[i] = 0ULL;
        gemm_h<2, 8>(sA + wrow * ASTR, ASTR, W2P, hb0, hb1, acc2, lane, bid, htid);

        float2 rf[16];  // refined values this thread owns
#pragma unroll
        for (int rr = 0; rr < 8; rr++) {
            float* ar = sA + (wrow + rr) * ASTR;
#pragma unroll
            for (int q = 0; q < 2; q++) {
                int c0 = q * 64 + 2 * lane;
                float2 bb = __ldg((const float2*)(b2 + c0));
                float2 v;
                v.x = sum2(acc2[rr * 4 + 2 * q + 0]) + bb.x;
                v.y = sum2(acc2[rr * 4 + 2 * q + 1]) + bb.y;
                rf[rr * 2 + q] = v;
                *(float2*)(ar + c0) = v;  // refined -> sA cols 0..127 (act dead)
            }
        }
        __syncwarp();

        // ---------- M3: z = state @ wg_s + refined @ wg_r (accumulated) ------
        u64 acc3[32];
#pragma unroll
        for (int i = 0; i < 32; i++) acc3[i] = 0ULL;
        gemm_h<2, 4>(sS + wrow * SSTR, SSTR, WGP, hb0, hb1, acc3, lane, bid, htid);
        gemm_h<2, 4>(sA + wrow * ASTR, ASTR, WGP + 16384, hb0, hb1, acc3, lane, bid, htid);

        // gate + residual update (same ownership -> warp-local)
#pragma unroll
        for (int rr = 0; rr < 8; rr++) {
            float* srw = sS + (wrow + rr) * SSTR;
#pragma unroll
            for (int q = 0; q < 2; q++) {
                int c0 = q * 64 + 2 * lane;
                float2 bb = __ldg((const float2*)(bg + c0));
                float g0 = sigmoid_f(sum2(acc3[rr * 4 + 2 * q + 0]) + bb.x);
                float g1 = sigmoid_f(sum2(acc3[rr * 4 + 2 * q + 1]) + bb.y);
                float2 st = *(const float2*)(srw + c0);
                st.x += g0 * rf[rr * 2 + q].x;
                st.y += g1 * rf[rr * 2 + q].y;
                *(float2*)(srw + c0) = st;
            }
        }
        __syncwarp();  // state visible warp-wide for next pass's LN
    }

    // ---- store result (block-strided; sync across warps once) ----
    __syncthreads();
    {
        float4* og = (float4*)(out + rowBase * 128);
#pragma unroll
        for (int i = 0; i < 8; i++) {
            int idx = tid + i * NTHREADS;
            og[idx] = *(const float4*)&sS[(idx >> 5) * SSTR + (idx & 31) * 4];
        }
    }
}

extern "C" void kernel_launch(void* const* d_in, const int* in_sizes, int n_in,
                              void* d_out, int out_size) {
    const float* x    = (const float*)d_in[0];
    const float* ln_w = (const float*)d_in[1];
    const float* ln_b = (const float*)d_in[2];
    const float* w1   = (const float*)d_in[3];
    const float* b1   = (const float*)d_in[4];
    const float* w2   = (const float*)d_in[5];
    const float* b2   = (const float*)d_in[6];
    const float* wg   = (const float*)d_in[7];
    const float* bg   = (const float*)d_in[8];
    const int* passes = (const int*)d_in[9];
    float* out = (float*)d_out;

    pack_weights_kernel<<<192, 256>>>(w1, w2, wg);

    const int nrows = in_sizes[0] / 128;
    const int blocks = nrows / TM;

    cudaFuncSetAttribute(TinyRecurrentWorkshop_69054484185493_kernel,
                         cudaFuncAttributeMaxDynamicSharedMemorySize, SMEM_BYTES);
    TinyRecurrentWorkshop_69054484185493_kernel<<<blocks, NTHREADS, SMEM_BYTES>>>(
        x, ln_w, ln_b, b1, b2, bg, passes, out);
}

// round 17
// speedup vs baseline: 1.0010x; 1.0002x over previous
#include <cuda_runtime.h>
#include <cstdint>
#include <math.h>

#define NTHREADS 256
#define TM 64
#define SSTR 132                     /* 132 % 4 == 0, 132 % 32 == 4 */
#define ASTR 260                     /* 260 % 4 == 0, 260 % 32 == 4 */
#define TILE_F 4096                  /* 16 KB weight tile */

#define SA_OFF (TM * SSTR)           /* 8448  */
#define SW_OFF (SA_OFF + TM * ASTR)  /* 25088 */
#define SMEM_FLOATS (SW_OFF + 4 * TILE_F) /* 41472 */
#define SMEM_BYTES (SMEM_FLOATS * 4)      /* 165888 B */

typedef unsigned long long u64;

// k-pair-interleaved weights (constant; packed once per launch)
__device__ float W1P[128 * 256];
__device__ float W2P[256 * 128];
__device__ float WGP[256 * 128];

// ---------------- packed f32x2 (Blackwell FFMA2) ----------------
__device__ __forceinline__ u64 fma2(u64 a, u64 b, u64 c) {
    u64 d;
    asm("fma.rn.f32x2 %0, %1, %2, %3;" : "=l"(d) : "l"(a), "l"(b), "l"(c));
    return d;
}
__device__ __forceinline__ float sum2(u64 v) {
    float lo, hi;
    asm("mov.b64 {%0, %1}, %2;" : "=f"(lo), "=f"(hi) : "l"(v));
    return lo + hi;
}

// ---------------- cp.async ----------------
__device__ __forceinline__ void cp_async16(unsigned saddr, const void* g) {
    asm volatile("cp.async.ca.shared.global [%0], [%1], 16;" ::"r"(saddr), "l"(g));
}
__device__ __forceinline__ void cp_commit() {
    asm volatile("cp.async.commit_group;" ::: "memory");
}
__device__ __forceinline__ void cp_wait0() {
    asm volatile("cp.async.wait_group 0;" ::: "memory");
}
// half-scoped named barrier (128 threads)
__device__ __forceinline__ void barh(int bid) {
    asm volatile("bar.sync %0, 128;" ::"r"(bid) : "memory");
}
// one 16KB tile loaded by 128 threads (8 float4 each)
__device__ __forceinline__ void ldtile128(float* dst, const float* g, int htid) {
    unsigned s = (unsigned)__cvta_generic_to_shared(dst);
    const float4* g4 = (const float4*)g;
#pragma unroll
    for (int i = 0; i < 8; i++)
        cp_async16(s + (htid + i * 128) * 16, g4 + htid + i * 128);
    cp_commit();
}

__device__ __forceinline__ float gelu_f(float x) {
    return 0.5f * x * (1.0f + erff(x * 0.7071067811865476f));
}
__device__ __forceinline__ float sigmoid_f(float x) {
    return 1.0f / (1.0f + __expf(-x));
}

// ---------------- weight pre-pack: out[kp][n] = (in[2kp][n], in[2kp+1][n]) ---
__global__ void pack_weights_kernel(const float* __restrict__ w1,
                                    const float* __restrict__ w2,
                                    const float* __restrict__ wg) {
    int i = blockIdx.x * blockDim.x + threadIdx.x;  // 0 .. 49151
    int m = i >> 14;
    int r = i & 16383;
    if (m == 0) {
        int kp = r >> 8, n = r & 255;
        ((float2*)W1P)[r] = make_float2(w1[(2 * kp) * 256 + n], w1[(2 * kp + 1) * 256 + n]);
    } else if (m == 1) {
        int kp = r >> 7, n = r & 127;
        ((float2*)W2P)[r] = make_float2(w2[(2 * kp) * 128 + n], w2[(2 * kp + 1) * 128 + n]);
    } else {
        int kp = r >> 7, n = r & 127;
        ((float2*)WGP)[r] = make_float2(wg[(2 * kp) * 128 + n], wg[(2 * kp + 1) * 128 + n]);
    }
}

// ---------------- k-paired GEMM, warp-owned 8 rows x (Q*64) u64-cols ---------
// Q=4: N=256 (M1). Q=2: N=128 (M2/M3). Thread owns u64 cols q*64 + 2*lane,
// q = 0..Q-1, each col pair as one u64 acc of (even-k, odd-k) partials.
// A: SMEM rows (stride astr), LDS.128 broadcast per row per 4k.
// B: k-pair-packed weights in global, streamed via two 16KB half-owned buffers
// with half-scoped named barriers. ACCUMULATES into acc.
template <int Q, int NTILES>
__device__ __forceinline__ void gemm_h(const float* __restrict__ A0, int astr,
                                       const float* __restrict__ Bg,
                                       float* b0, float* b1, u64* acc,
                                       int lane, int bid, int htid) {
    constexpr int KQ = 16 / Q;  // kq (4k each) per tile
    ldtile128(b0, Bg, htid);
    cp_wait0();
    barh(bid);
    for (int t = 0; t < NTILES; t++) {
        if (t + 1 < NTILES)
            ldtile128(((t + 1) & 1) ? b1 : b0, Bg + (t + 1) * TILE_F, htid);
        const float* sB = (t & 1) ? b1 : b0;
        const float* At = A0 + t * (KQ * 4);
#pragma unroll
        for (int kq = 0; kq < KQ; kq++) {
            ulonglong2 a[8];
#pragma unroll
            for (int rr = 0; rr < 8; rr++)
                a[rr] = *(const ulonglong2*)(At + rr * astr + kq * 4);
#pragma unroll
            for (int j = 0; j < 2; j++) {
                const u64* bp = (const u64*)sB + (kq * 2 + j) * (Q * 64) + 2 * lane;
                u64 b[2 * Q];
#pragma unroll
                for (int q = 0; q < Q; q++)
                    *(ulonglong2*)&b[2 * q] = *(const ulonglong2*)(bp + q * 64);
#pragma unroll
                for (int rr = 0; rr < 8; rr++) {
                    u64 av = j ? a[rr].y : a[rr].x;
#pragma unroll
                    for (int c = 0; c < 2 * Q; c++)
                        acc[rr * 2 * Q + c] = fma2(av, b[c], acc[rr * 2 * Q + c]);
                }
            }
        }
        cp_wait0();
        barh(bid);
    }
}

// ---------------- main fused recurrent kernel ----------------
__global__ void __launch_bounds__(NTHREADS, 1)
TinyRecurrentWorkshop_69054484185493_kernel(
    const float* __restrict__ x,
    const float* __restrict__ ln_w, const float* __restrict__ ln_b,
    const float* __restrict__ b1, const float* __restrict__ b2,
    const float* __restrict__ bg,
    const int* __restrict__ passes_p,
    float* __restrict__ out) {
    extern __shared__ float smem[];
    float* sS = smem;            // state 64 x 132
    float* sA = smem + SA_OFF;   // h / act / refined : 64 x 260
    float* sW = smem + SW_OFF;   // 2 halves x 2 x 4096 weight buffers

    const int tid = threadIdx.x;
    const int w = tid >> 5, lane = tid & 31;
    const int half = tid >> 7, htid = tid & 127;
    const int bid = 1 + half;           // named barrier id per half
    const int wrow = w * 8;             // this warp's 8 rows (all phases)
    float* hb0 = sW + half * 2 * TILE_F;
    float* hb1 = hb0 + TILE_F;
    const long long rowBase = (long long)blockIdx.x * TM;

    // ---- load state tile (block-strided, one CTA sync) ----
    {
        const float4* xg = (const float4*)(x + rowBase * 128);
#pragma unroll
        for (int i = 0; i < 8; i++) {
            int idx = tid + i * NTHREADS;
            *(float4*)&sS[(idx >> 5) * SSTR + (idx & 31) * 4] = xg[idx];
        }
    }

    int npass = passes_p[0];
    if (npass < 1 || npass > 1024) {
        float f = __int_as_float(npass);
        npass = (int)f;
        if (npass < 1 || npass > 1024) npass = 8;
    }
    __syncthreads();

    const int r4 = lane >> 2;   // LN: 4 lanes per row, 8 rows per warp
    const int lq = lane & 3;

    for (int pass = 0; pass < npass; pass++) {
        // ---------- LayerNorm (warp-local): sS rows -> h in sA[:,0:128] ------
        {
            float4 xv[8];
            const float* sr = sS + (wrow + r4) * SSTR + lq * 32;
            float s = 0.f;
#pragma unroll
            for (int j = 0; j < 8; j++) {
                xv[j] = *(const float4*)(sr + j * 4);
                s += (xv[j].x + xv[j].y) + (xv[j].z + xv[j].w);
            }
            s += __shfl_xor_sync(0xFFFFFFFFu, s, 1);
            s += __shfl_xor_sync(0xFFFFFFFFu, s, 2);
            const float mu = s * (1.0f / 128.0f);
            float q = 0.f;
#pragma unroll
            for (int j = 0; j < 8; j++) {
                float d0 = xv[j].x - mu, d1 = xv[j].y - mu;
                float d2 = xv[j].z - mu, d3 = xv[j].w - mu;
                q += d0 * d0 + d1 * d1 + d2 * d2 + d3 * d3;
            }
            q += __shfl_xor_sync(0xFFFFFFFFu, q, 1);
            q += __shfl_xor_sync(0xFFFFFFFFu, q, 2);
            const float rstd = rsqrtf(q * (1.0f / 128.0f) + 1e-5f);
            float* hr = sA + (wrow + r4) * ASTR + lq * 32;
#pragma unroll
            for (int j = 0; j < 8; j++) {
                float4 wv = __ldg((const float4*)ln_w + lq * 8 + j);
                float4 bv = __ldg((const float4*)ln_b + lq * 8 + j);
                float4 h;
                h.x = (xv[j].x - mu) * rstd * wv.x + bv.x;
                h.y = (xv[j].y - mu) * rstd * wv.y + bv.y;
                h.z = (xv[j].z - mu) * rstd * wv.z + bv.z;
                h.w = (xv[j].w - mu) * rstd * wv.w + bv.w;
                *(float4*)(hr + j * 4) = h;
            }
        }
        __syncwarp();  // h visible warp-wide (A reads broadcast across lanes)

        // ---------- M1: g = h @ w1  (rows own, N=256, K=128) ----------
        u64 acc1[64];
#pragma unroll
        for (int i = 0; i < 64; i++) acc1[i] = 0ULL;
        gemm_h<4, 8>(sA + wrow * ASTR, ASTR, W1P, hb0, hb1, acc1, lane, bid, htid);

        // gelu(g + b1) -> sA rows own, cols 0..255
#pragma unroll
        for (int rr = 0; rr < 8; rr++) {
            float* ar = sA + (wrow + rr) * ASTR;
#pragma unroll
            for (int q = 0; q < 4; q++) {
                int c0 = q * 64 + 2 * lane;
                float2 bb = __ldg((const float2*)(b1 + c0));
                float2 o;
                o.x = gelu_f(sum2(acc1[rr * 8 + 2 * q + 0]) + bb.x);
                o.y = gelu_f(sum2(acc1[rr * 8 + 2 * q + 1]) + bb.y);
                *(float2*)(ar + c0) = o;
            }
        }
        __syncwarp();

        // ---------- M2: refined = act @ w2 + b2  (N=128, K=256) ----------
        u64 acc2[32];
#pragma unroll
        for (int i = 0; i < 32; i++) acc2[i] = 0ULL;
        gemm_h<2, 8>(sA + wrow * ASTR, ASTR, W2P, hb0, hb1, acc2, lane, bid, htid);

        float2 rf[16];  // refined values this thread owns
#pragma unroll
        for (int rr = 0; rr < 8; rr++) {
            float* ar = sA + (wrow + rr) * ASTR;
#pragma unroll
            for (int q = 0; q < 2; q++) {
                int c0 = q * 64 + 2 * lane;
                float2 bb = __ldg((const float2*)(b2 + c0));
                float2 v;
                v.x = sum2(acc2[rr * 4 + 2 * q + 0]) + bb.x;
                v.y = sum2(acc2[rr * 4 + 2 * q + 1]) + bb.y;
                rf[rr * 2 + q] = v;
                *(float2*)(ar + c0) = v;  // refined -> sA cols 0..127 (act dead)
            }
        }
        __syncwarp();

        // ---------- M3: z = state @ wg_s + refined @ wg_r (accumulated) ------
        u64 acc3[32];
#pragma unroll
        for (int i = 0; i < 32; i++) acc3[i] = 0ULL;
        gemm_h<2, 4>(sS + wrow * SSTR, SSTR, WGP, hb0, hb1, acc3, lane, bid, htid);
        gemm_h<2, 4>(sA + wrow * ASTR, ASTR, WGP + 16384, hb0, hb1, acc3, lane, bid, htid);

        // gate + residual update (same ownership -> warp-local)
#pragma unroll
        for (int rr = 0; rr < 8; rr++) {
            float* srw = sS + (wrow + rr) * SSTR;
#pragma unroll
            for (int q = 0; q < 2; q++) {
                int c0 = q * 64 + 2 * lane;
                float2 bb = __ldg((const float2*)(bg + c0));
                float g0 = sigmoid_f(sum2(acc3[rr * 4 + 2 * q + 0]) + bb.x);
                float g1 = sigmoid_f(sum2(acc3[rr * 4 + 2 * q + 1]) + bb.y);
                float2 st = *(const float2*)(srw + c0);
                st.x += g0 * rf[rr * 2 + q].x;
                st.y += g1 * rf[rr * 2 + q].y;
                *(float2*)(srw + c0) = st;
            }
        }
        __syncwarp();  // state visible warp-wide for next pass's LN
    }

    // ---- store result (block-strided; sync across warps once) ----
    __syncthreads();
    {
        float4* og = (float4*)(out + rowBase * 128);
#pragma unroll
        for (int i = 0; i < 8; i++) {
            int idx = tid + i * NTHREADS;
            og[idx] = *(const float4*)&sS[(idx >> 5) * SSTR + (idx & 31) * 4];
        }
    }
}

extern "C" void kernel_launch(void* const* d_in, const int* in_sizes, int n_in,
                              void* d_out, int out_size) {
    const float* x    = (const float*)d_in[0];
    const float* ln_w = (const float*)d_in[1];
    const float* ln_b = (const float*)d_in[2];
    const float* w1   = (const float*)d_in[3];
    const float* b1   = (const float*)d_in[4];
    const float* w2   = (const float*)d_in[5];
    const float* b2   = (const float*)d_in[6];
    const float* wg   = (const float*)d_in[7];
    const float* bg   = (const float*)d_in[8];
    const int* passes = (const int*)d_in[9];
    float* out = (float*)d_out;

    pack_weights_kernel<<<192, 256>>>(w1, w2, wg);

    const int nrows = in_sizes[0] / 128;
    const int blocks = nrows / TM;

    cudaFuncSetAttribute(TinyRecurrentWorkshop_69054484185493_kernel,
                         cudaFuncAttributeMaxDynamicSharedMemorySize, SMEM_BYTES);
    TinyRecurrentWorkshop_69054484185493_kernel<<<blocks, NTHREADS, SMEM_BYTES>>>(
        x, ln_w, ln_b, b1, b2, bg, passes, out);
}